// round 6
// baseline (speedup 1.0000x reference)
#include <cuda_runtime.h>
#include <cuda_bf16.h>
#include <math.h>
#include <stdint.h>

#define NB    8
#define LQ    1000
#define DM    256
#define NH    8
#define DH    32
#define NLV   4
#define NPT   4
#define LEN_IN 21760
#define DFFN  1024
#define NQ    (NB*LQ)    /* 8000 */
#define NSRC  (NB*LEN_IN) /* 174080 */

// ---------------- fp32 scratch ---------------------------------------------
__device__ float g_qkc[NQ*512];          // merged q|k projections
__device__ float g_v[NQ*DM];
__device__ float g_proj[NQ*DM];
__device__ float g_tgt2[NQ*DM];
__device__ float g_tgt3[NQ*DM];
__device__ float g_offaw[NQ*384];        // merged offsets|aw
__device__ float g_value[(size_t)NSRC*DM];
__device__ float g_cbias[384];

// ---------------- bf16 hi/lo split scratch ---------------------------------
__device__ __nv_bfloat16 g_qk_h[NQ*DM],   g_qk_l[NQ*DM];
__device__ __nv_bfloat16 g_tgt_h[NQ*DM],  g_tgt_l[NQ*DM];
__device__ __nv_bfloat16 g_att_h[NQ*DM],  g_att_l[NQ*DM];
__device__ __nv_bfloat16 g_query_h[NQ*DM],g_query_l[NQ*DM];
__device__ __nv_bfloat16 g_tgt3_h[NQ*DM], g_tgt3_l[NQ*DM];
__device__ __nv_bfloat16 g_ca_h[NQ*DM],   g_ca_l[NQ*DM];
__device__ __nv_bfloat16 g_ffn_h[NQ*DFFN],g_ffn_l[NQ*DFFN];
__device__ __nv_bfloat16 g_src_h[(size_t)NSRC*DM], g_src_l[(size_t)NSRC*DM];

#define WTOT 1015808
#define OFF_SAIN  0
#define OFF_SAOUT 196608
#define OFF_OFFW  262144   /* off weights then aw weights: contiguous N=384 */
#define OFF_AWW   327680
#define OFF_VALW  360448
#define OFF_OUTPW 425984
#define OFF_FFN1  491520
#define OFF_FFN2  753664
__device__ __nv_bfloat16 g_wh[WTOT], g_wl[WTOT];

// =================== helpers ===============================================
__device__ __forceinline__ uint32_t smem_u32(const void* p) {
    uint32_t a;
    asm("{ .reg .u64 t; cvta.to.shared.u64 t, %1; cvt.u32.u64 %0, t; }" : "=r"(a) : "l"(p));
    return a;
}
__device__ __forceinline__ void ldmx4(uint32_t addr, uint32_t* r) {
    asm volatile("ldmatrix.sync.aligned.m8n8.x4.shared.b16 {%0,%1,%2,%3}, [%4];"
                 : "=r"(r[0]), "=r"(r[1]), "=r"(r[2]), "=r"(r[3]) : "r"(addr));
}
__device__ __forceinline__ void mma16816(float* d, const uint32_t* a, uint32_t b0, uint32_t b1) {
    asm volatile("mma.sync.aligned.m16n8k16.row.col.f32.bf16.bf16.f32 "
                 "{%0,%1,%2,%3}, {%4,%5,%6,%7}, {%8,%9}, {%0,%1,%2,%3};"
                 : "+f"(d[0]), "+f"(d[1]), "+f"(d[2]), "+f"(d[3])
                 : "r"(a[0]), "r"(a[1]), "r"(a[2]), "r"(a[3]), "r"(b0), "r"(b1));
}
__device__ __forceinline__ void cp16z(uint32_t dst, const void* src, bool v) {
    asm volatile("cp.async.cg.shared.global [%0], [%1], 16, %2;"
                 :: "r"(dst), "l"(src), "r"(v ? 16 : 0));
}
__device__ __forceinline__ void split2(float v, __nv_bfloat16& h, __nv_bfloat16& l) {
    h = __float2bfloat16(v);
    l = __float2bfloat16(v - __bfloat162float(h));
}

// =================== bf16-split tensor GEMM ================================
// C[M,N] = A[M,K] @ B[N,K]^T + bias.  64x128 tile, BK=32, 128 threads
// (4 warps, warp tile 32x64), 3-stage cp.async ring -> 2 CTAs/SM.
#define TCSTR 40                 /* smem row stride elems (80B) */
#define TILE_AH 0
#define TILE_AL 5120
#define TILE_BH 10240
#define TILE_BL 20480
#define STAGE_TOTAL 30720
#define NSTAGE 3
#define TCG_SMEM (NSTAGE*STAGE_TOTAL)

__device__ __forceinline__ void stage_load(
    uint32_t sb, const __nv_bfloat16* Ah, const __nv_bfloat16* Al,
    const __nv_bfloat16* Bh, const __nv_bfloat16* Bl,
    int M, int N, int K, int rowBase, int colBase, int k0, int tid) {
    // A: 64 rows x 64B; 128 threads -> row=tid>>1, 32B half per thread
    {
        const int r = tid >> 1, cb = (tid & 1) * 32;
        int gr = rowBase + r; bool av = gr < M; if (!av) gr = 0;
        const char* pa  = (const char*)(Ah + (size_t)gr * K + k0) + cb;
        const char* pal = (const char*)(Al + (size_t)gr * K + k0) + cb;
        uint32_t da  = sb + TILE_AH + r * 80 + cb;
        uint32_t dal = sb + TILE_AL + r * 80 + cb;
        cp16z(da, pa, av);       cp16z(da + 16, pa + 16, av);
        cp16z(dal, pal, av);     cp16z(dal + 16, pal + 16, av);
    }
    // B: 128 rows x 64B; one row per thread
    {
        const int r = tid;
        int gc = colBase + r; bool bv = gc < N; if (!bv) gc = 0;
        const char* pb  = (const char*)(Bh + (size_t)gc * K + k0);
        const char* pbl = (const char*)(Bl + (size_t)gc * K + k0);
        uint32_t db  = sb + TILE_BH + r * 80;
        uint32_t dbl = sb + TILE_BL + r * 80;
        #pragma unroll
        for (int j = 0; j < 4; j++) {
            cp16z(db + j * 16, pb + j * 16, bv);
            cp16z(dbl + j * 16, pbl + j * 16, bv);
        }
    }
    asm volatile("cp.async.commit_group;" ::: "memory");
}

template<bool RELU, bool SPLITOUT>
__global__ __launch_bounds__(128)
void tc_gemm_bf(const __nv_bfloat16* __restrict__ Ah, const __nv_bfloat16* __restrict__ Al,
                const __nv_bfloat16* __restrict__ Bh, const __nv_bfloat16* __restrict__ Bl,
                const float* __restrict__ bias, float* __restrict__ Cf,
                __nv_bfloat16* __restrict__ Chi, __nv_bfloat16* __restrict__ Clo,
                int M, int N, int K) {
    extern __shared__ char smem[];
    const uint32_t sbase = smem_u32(smem);
    const int tid  = threadIdx.x;
    const int lane = tid & 31;
    const int wid  = tid >> 5;
    const int warpM = wid & 1;            // rows warpM*32
    const int warpN = wid >> 1;           // cols warpN*64
    const int rowBase = blockIdx.y * 64;
    const int colBase = blockIdx.x * 128;

    const int aRow = (lane & 15);
    const int aColOff = (lane >> 4) * 8;
    const int bRow = (lane & 7) + ((lane >> 4) & 1) * 8;
    const int bColOff = ((lane >> 3) & 1) * 8;

    float acc[2][8][4];
    #pragma unroll
    for (int mt = 0; mt < 2; mt++)
        #pragma unroll
        for (int nt = 0; nt < 8; nt++)
            #pragma unroll
            for (int i = 0; i < 4; i++) acc[mt][nt][i] = 0.f;

    const int KC = K >> 5;
    #pragma unroll
    for (int s = 0; s < NSTAGE - 1; s++)
        if (s < KC)
            stage_load(sbase + s * STAGE_TOTAL, Ah, Al, Bh, Bl,
                       M, N, K, rowBase, colBase, s << 5, tid);

    for (int c = 0; c < KC; c++) {
        asm volatile("cp.async.wait_group %0;" :: "n"(NSTAGE - 2) : "memory");
        __syncthreads();
        if (c + NSTAGE - 1 < KC)
            stage_load(sbase + ((c + NSTAGE - 1) % NSTAGE) * STAGE_TOTAL, Ah, Al, Bh, Bl,
                       M, N, K, rowBase, colBase, (c + NSTAGE - 1) << 5, tid);

        const uint32_t sb = sbase + (c % NSTAGE) * STAGE_TOTAL;
        #pragma unroll
        for (int ks = 0; ks < 32; ks += 16) {
            uint32_t ah[2][4], al[2][4];
            #pragma unroll
            for (int mt = 0; mt < 2; mt++) {
                const int r0 = warpM * 32 + mt * 16;
                uint32_t off = (uint32_t)((r0 + aRow) * TCSTR + ks + aColOff) * 2;
                ldmx4(sb + TILE_AH + off, ah[mt]);
                ldmx4(sb + TILE_AL + off, al[mt]);
            }
            uint32_t bh[4][4], bl[4][4];
            #pragma unroll
            for (int nb = 0; nb < 4; nb++) {
                const int n0 = warpN * 64 + nb * 16;
                uint32_t off = (uint32_t)((n0 + bRow) * TCSTR + ks + bColOff) * 2;
                ldmx4(sb + TILE_BH + off, bh[nb]);
                ldmx4(sb + TILE_BL + off, bl[nb]);
            }
            #pragma unroll
            for (int mt = 0; mt < 2; mt++) {
                #pragma unroll
                for (int nt = 0; nt < 8; nt++) {
                    const int nb = nt >> 1, hi = (nt & 1) * 2;
                    mma16816(acc[mt][nt], ah[mt], bh[nb][hi], bh[nb][hi+1]);
                    mma16816(acc[mt][nt], ah[mt], bl[nb][hi], bl[nb][hi+1]);
                    mma16816(acc[mt][nt], al[mt], bh[nb][hi], bh[nb][hi+1]);
                }
            }
        }
    }

    // ---- epilogue ---------------------------------------------------------
    #pragma unroll
    for (int mt = 0; mt < 2; mt++) {
        #pragma unroll
        for (int half = 0; half < 2; half++) {
            const int row = rowBase + warpM * 32 + mt * 16 + (lane >> 2) + half * 8;
            if (row < M) {
                #pragma unroll
                for (int nt = 0; nt < 8; nt++) {
                    const int col = colBase + warpN * 64 + nt * 8 + (lane & 3) * 2;
                    float ox = acc[mt][nt][half*2+0] + bias[col];
                    float oy = acc[mt][nt][half*2+1] + bias[col+1];
                    if (RELU) { ox = fmaxf(ox, 0.f); oy = fmaxf(oy, 0.f); }
                    if (SPLITOUT) {
                        __nv_bfloat16 hx, lx, hy, ly;
                        split2(ox, hx, lx); split2(oy, hy, ly);
                        *(__nv_bfloat162*)(Chi + (size_t)row * N + col) = __nv_bfloat162(hx, hy);
                        *(__nv_bfloat162*)(Clo + (size_t)row * N + col) = __nv_bfloat162(lx, ly);
                    } else {
                        *(float2*)(Cf + (size_t)row * N + col) = make_float2(ox, oy);
                    }
                }
            }
        }
    }
}

// ---------------- weight splitter + combined bias --------------------------
__global__ void split_weights(const float* __restrict__ w0, const float* __restrict__ w1,
                              const float* __restrict__ w2, const float* __restrict__ w3,
                              const float* __restrict__ w4, const float* __restrict__ w5,
                              const float* __restrict__ w6, const float* __restrict__ w7,
                              const float* __restrict__ off_b, const float* __restrict__ aw_b,
                              __nv_bfloat16* __restrict__ hi, __nv_bfloat16* __restrict__ lo,
                              float* __restrict__ cbias) {
    int i = blockIdx.x * blockDim.x + threadIdx.x;
    if (i < 384) cbias[i] = (i < 256) ? off_b[i] : aw_b[i - 256];
    if (i >= WTOT) return;
    const float* src; int local;
    if      (i < OFF_SAOUT) { src = w0; local = i; }
    else if (i < OFF_OFFW)  { src = w1; local = i - OFF_SAOUT; }
    else if (i < OFF_AWW)   { src = w2; local = i - OFF_OFFW; }
    else if (i < OFF_VALW)  { src = w3; local = i - OFF_AWW; }
    else if (i < OFF_OUTPW) { src = w4; local = i - OFF_VALW; }
    else if (i < OFF_FFN1)  { src = w5; local = i - OFF_OUTPW; }
    else if (i < OFF_FFN2)  { src = w6; local = i - OFF_FFN1; }
    else                    { src = w7; local = i - OFF_FFN2; }
    __nv_bfloat16 h, l;
    split2(src[local], h, l);
    hi[i] = h; lo[i] = l;
}

// ---------------- add + split: qk = tgt+pos; also split tgt ----------------
__global__ void add_split_kernel(const float* __restrict__ a, const float* __restrict__ b,
                                 __nv_bfloat16* __restrict__ qh, __nv_bfloat16* __restrict__ ql,
                                 __nv_bfloat16* __restrict__ th, __nv_bfloat16* __restrict__ tl,
                                 int n4) {
    int i = blockIdx.x * blockDim.x + threadIdx.x;
    if (i >= n4) return;
    float4 x = ((const float4*)a)[i];
    float4 y = ((const float4*)b)[i];
    float q0 = x.x + y.x, q1 = x.y + y.y, q2 = x.z + y.z, q3 = x.w + y.w;
    __nv_bfloat16 h0,l0,h1,l1,h2,l2,h3,l3;
    split2(q0,h0,l0); split2(q1,h1,l1); split2(q2,h2,l2); split2(q3,h3,l3);
    *(__nv_bfloat162*)(qh + i*4)     = __nv_bfloat162(h0,h1);
    *(__nv_bfloat162*)(qh + i*4 + 2) = __nv_bfloat162(h2,h3);
    *(__nv_bfloat162*)(ql + i*4)     = __nv_bfloat162(l0,l1);
    *(__nv_bfloat162*)(ql + i*4 + 2) = __nv_bfloat162(l2,l3);
    split2(x.x,h0,l0); split2(x.y,h1,l1); split2(x.z,h2,l2); split2(x.w,h3,l3);
    *(__nv_bfloat162*)(th + i*4)     = __nv_bfloat162(h0,h1);
    *(__nv_bfloat162*)(th + i*4 + 2) = __nv_bfloat162(h2,h3);
    *(__nv_bfloat162*)(tl + i*4)     = __nv_bfloat162(l0,l1);
    *(__nv_bfloat162*)(tl + i*4 + 2) = __nv_bfloat162(l2,l3);
}

// ---------------- generic fp32 -> hi/lo splitter (for src) -----------------
__global__ void split_kernel(const float* __restrict__ a,
                             __nv_bfloat16* __restrict__ hi, __nv_bfloat16* __restrict__ lo,
                             int n4) {
    int i = blockIdx.x * blockDim.x + threadIdx.x;
    if (i >= n4) return;
    float4 x = ((const float4*)a)[i];
    __nv_bfloat16 h0,l0,h1,l1,h2,l2,h3,l3;
    split2(x.x,h0,l0); split2(x.y,h1,l1); split2(x.z,h2,l2); split2(x.w,h3,l3);
    *(__nv_bfloat162*)(hi + i*4)     = __nv_bfloat162(h0,h1);
    *(__nv_bfloat162*)(hi + i*4 + 2) = __nv_bfloat162(h2,h3);
    *(__nv_bfloat162*)(lo + i*4)     = __nv_bfloat162(l0,l1);
    *(__nv_bfloat162*)(lo + i*4 + 2) = __nv_bfloat162(l2,l3);
}

// ---------------- flash self-attention; q|k in merged [NQ,512] buffer ------
__global__ __launch_bounds__(128)
void attn_kernel(const float* __restrict__ qkc, const float* __restrict__ v,
                 __nv_bfloat16* __restrict__ oh, __nv_bfloat16* __restrict__ ol) {
    const int bh = blockIdx.y;
    const int b = bh / NH, h = bh % NH;
    const int qi = blockIdx.x * 128 + threadIdx.x;
    const bool valid = qi < LQ;
    const float scale = 0.1767766952966369f;

    const float* qb = qkc + (size_t)b * LQ * 512 + h * DH;
    const float* kb = qkc + (size_t)b * LQ * 512 + 256 + h * DH;
    const float* vb = v + (size_t)b * LQ * DM + h * DH;

    __shared__ float ks[32][32];
    __shared__ float vs[32][32];

    float qr[32];
    if (valid) {
        #pragma unroll
        for (int c = 0; c < 8; c++) {
            float4 t = *(const float4*)(qb + (size_t)qi * 512 + c * 4);
            qr[c*4+0] = t.x; qr[c*4+1] = t.y; qr[c*4+2] = t.z; qr[c*4+3] = t.w;
        }
    }

    float m = -1e30f, l = 0.f;
    float accv[32];
    #pragma unroll
    for (int d = 0; d < 32; d++) accv[d] = 0.f;

    for (int kt = 0; kt < LQ; kt += 32) {
        #pragma unroll
        for (int i = threadIdx.x; i < 256; i += 128) {
            int r = i >> 3, c4 = (i & 7) * 4;
            int kr = kt + r;
            float4 kv = make_float4(0.f,0.f,0.f,0.f), vv = kv;
            if (kr < LQ) {
                kv = *(const float4*)(kb + (size_t)kr * 512 + c4);
                vv = *(const float4*)(vb + (size_t)kr * DM + c4);
            }
            *(float4*)&ks[r][c4] = kv;
            *(float4*)&vs[r][c4] = vv;
        }
        __syncthreads();

        if (valid) {
            int nk = LQ - kt; if (nk > 32) nk = 32;
            float s[32];
            float tmax = -1e30f;
            #pragma unroll
            for (int j = 0; j < 32; j++) {
                if (j < nk) {
                    const float4* kr4 = (const float4*)ks[j];
                    float dot = 0.f;
                    #pragma unroll
                    for (int c = 0; c < 8; c++) {
                        float4 kk = kr4[c];
                        dot = fmaf(qr[c*4+0], kk.x, dot);
                        dot = fmaf(qr[c*4+1], kk.y, dot);
                        dot = fmaf(qr[c*4+2], kk.z, dot);
                        dot = fmaf(qr[c*4+3], kk.w, dot);
                    }
                    s[j] = dot * scale;
                    tmax = fmaxf(tmax, s[j]);
                } else s[j] = -1e30f;
            }
            float mnew = fmaxf(m, tmax);
            float corr = __expf(m - mnew);
            l *= corr;
            #pragma unroll
            for (int d = 0; d < 32; d++) accv[d] *= corr;
            #pragma unroll
            for (int j = 0; j < 32; j++) {
                float p = __expf(s[j] - mnew);
                l += p;
                const float4* vr4 = (const float4*)vs[j];
                #pragma unroll
                for (int c = 0; c < 8; c++) {
                    float4 vv = vr4[c];
                    accv[c*4+0] = fmaf(p, vv.x, accv[c*4+0]);
                    accv[c*4+1] = fmaf(p, vv.y, accv[c*4+1]);
                    accv[c*4+2] = fmaf(p, vv.z, accv[c*4+2]);
                    accv[c*4+3] = fmaf(p, vv.w, accv[c*4+3]);
                }
            }
            m = mnew;
        }
        __syncthreads();
    }

    if (valid) {
        float inv = 1.f / l;
        size_t base = ((size_t)b * LQ + qi) * DM + h * DH;
        #pragma unroll
        for (int d = 0; d < 32; d += 2) {
            float v0 = accv[d] * inv, v1 = accv[d+1] * inv;
            __nv_bfloat16 h0,l0,h1,l1;
            split2(v0,h0,l0); split2(v1,h1,l1);
            *(__nv_bfloat162*)(oh + base + d) = __nv_bfloat162(h0,h1);
            *(__nv_bfloat162*)(ol + base + d) = __nv_bfloat162(l0,l1);
        }
    }
}

// ---------------- LayerNorm(x+res) -> fp32 out (+ optional split of out+pos)
__global__ __launch_bounds__(256)
void ln_kernel(const float* __restrict__ x, const float* __restrict__ res,
               const float* __restrict__ g, const float* __restrict__ bta,
               float* __restrict__ out,
               const float* __restrict__ pos,
               __nv_bfloat16* __restrict__ hi, __nv_bfloat16* __restrict__ lo) {
    __shared__ float red[8];
    const int row = blockIdx.x, t = threadIdx.x;
    const size_t idx = (size_t)row * DM + t;
    float v = x[idx] + res[idx];

    float s = v;
    #pragma unroll
    for (int o = 16; o; o >>= 1) s += __shfl_xor_sync(0xffffffffu, s, o);
    if ((t & 31) == 0) red[t >> 5] = s;
    __syncthreads();
    float mean = 0.f;
    #pragma unroll
    for (int i = 0; i < 8; i++) mean += red[i];
    mean *= (1.f / DM);
    __syncthreads();

    float d = v - mean;
    float s2 = d * d;
    #pragma unroll
    for (int o = 16; o; o >>= 1) s2 += __shfl_xor_sync(0xffffffffu, s2, o);
    if ((t & 31) == 0) red[t >> 5] = s2;
    __syncthreads();
    float var = 0.f;
    #pragma unroll
    for (int i = 0; i < 8; i++) var += red[i];
    var *= (1.f / DM);

    float o = d * rsqrtf(var + 1e-5f) * g[t] + bta[t];
    out[idx] = o;
    if (hi) {
        float tq = pos ? o + pos[idx] : o;
        __nv_bfloat16 hh, ll;
        split2(tq, hh, ll);
        hi[idx] = hh; lo[idx] = ll;
    }
}

// ---------------- attention-weight softmax (aw at offset 256 of g_offaw) ---
__global__ void awsm_kernel(float* __restrict__ offaw) {
    int i = blockIdx.x * blockDim.x + threadIdx.x;
    if (i >= NQ * NH) return;
    float* p = offaw + (size_t)(i / NH) * 384 + 256 + (i % NH) * 16;
    float mx = -1e30f;
    #pragma unroll
    for (int j = 0; j < 16; j++) mx = fmaxf(mx, p[j]);
    float sm = 0.f, e[16];
    #pragma unroll
    for (int j = 0; j < 16; j++) { e[j] = __expf(p[j] - mx); sm += e[j]; }
    float inv = 1.f / sm;
    #pragma unroll
    for (int j = 0; j < 16; j++) p[j] = e[j] * inv;
}

// ---------------- MS-deformable sampling, reads merged offaw ---------------
__global__ __launch_bounds__(256)
void deform_kernel(const float* __restrict__ value, const float* __restrict__ offaw,
                   const float* __restrict__ ref,
                   __nv_bfloat16* __restrict__ oh, __nv_bfloat16* __restrict__ ol) {
    const int qidx = blockIdx.x;
    const int b = qidx / LQ;
    const int h = threadIdx.y, d = threadIdx.x;

    const int starts[4] = {0, 16384, 20480, 21504};
    const int Wi[4]     = {128, 64, 32, 16};

    const float* vb = value + (size_t)b * LEN_IN * DM + h * DH + d;
    const size_t oq = (size_t)qidx;
    const float* offp = offaw + oq * 384;
    float acc = 0.f;

    #pragma unroll
    for (int lvl = 0; lvl < NLV; lvl++) {
        const float W = (float)Wi[lvl];
        const int   Wl = Wi[lvl];
        const int   st = starts[lvl];
        const float rx = ref[(oq * NLV + lvl) * 2 + 0];
        const float ry = ref[(oq * NLV + lvl) * 2 + 1];
        #pragma unroll
        for (int p = 0; p < NPT; p++) {
            const int oidx = ((h * NLV + lvl) * NPT + p) * 2;
            const float ox = offp[oidx + 0];
            const float oy = offp[oidx + 1];
            const float a  = offp[256 + h * 16 + lvl * 4 + p];
            const float x = (rx + ox / W) * W - 0.5f;
            const float y = (ry + oy / W) * W - 0.5f;
            const float x0f = floorf(x), y0f = floorf(y);
            const float lx = x - x0f, ly = y - y0f;
            const int x0 = (int)x0f, y0 = (int)y0f;

            const float w00 = (1.f - ly) * (1.f - lx);
            const float w01 = (1.f - ly) * lx;
            const float w10 = ly * (1.f - lx);
            const float w11 = ly * lx;

            const bool xv0 = (x0 >= 0) & (x0 < Wl);
            const bool xv1 = (x0 + 1 >= 0) & (x0 + 1 < Wl);
            const bool yv0 = (y0 >= 0) & (y0 < Wl);
            const bool yv1 = (y0 + 1 >= 0) & (y0 + 1 < Wl);

            if (yv0 & xv0) acc = fmaf(a * w00, vb[(size_t)(st + y0 * Wl + x0) * DM], acc);
            if (yv0 & xv1) acc = fmaf(a * w01, vb[(size_t)(st + y0 * Wl + x0 + 1) * DM], acc);
            if (yv1 & xv0) acc = fmaf(a * w10, vb[(size_t)(st + (y0 + 1) * Wl + x0) * DM], acc);
            if (yv1 & xv1) acc = fmaf(a * w11, vb[(size_t)(st + (y0 + 1) * Wl + x0 + 1) * DM], acc);
        }
    }
    __nv_bfloat16 hh, ll;
    split2(acc, hh, ll);
    oh[oq * DM + h * DH + d] = hh;
    ol[oq * DM + h * DH + d] = ll;
}

// ---------------- host-side orchestration ----------------------------------
static inline void gemm_bf(const __nv_bfloat16* Ah, const __nv_bfloat16* Al,
                           const __nv_bfloat16* Bh, const __nv_bfloat16* Bl,
                           const float* bias, float* Cf,
                           __nv_bfloat16* Chi, __nv_bfloat16* Clo,
                           int M, int N, int K, bool relu_split) {
    dim3 grid(N / 128, (M + 63) / 64);
    if (relu_split)
        tc_gemm_bf<true, true><<<grid, 128, TCG_SMEM>>>(Ah, Al, Bh, Bl, bias, Cf, Chi, Clo, M, N, K);
    else
        tc_gemm_bf<false, false><<<grid, 128, TCG_SMEM>>>(Ah, Al, Bh, Bl, bias, Cf, Chi, Clo, M, N, K);
}

extern "C" void kernel_launch(void* const* d_in, const int* in_sizes, int n_in,
                              void* d_out, int out_size) {
    (void)in_sizes; (void)n_in; (void)out_size;
    const float* tgt       = (const float*)d_in[0];
    const float* query_pos = (const float*)d_in[1];
    const float* refpts    = (const float*)d_in[2];
    const float* src       = (const float*)d_in[3];
    const float* sa_in_b   = (const float*)d_in[7];
    const float* sa_out_b  = (const float*)d_in[9];
    const float* norm2_g   = (const float*)d_in[10];
    const float* norm2_b   = (const float*)d_in[11];
    const float* off_b     = (const float*)d_in[13];
    const float* aw_b      = (const float*)d_in[15];
    const float* val_b     = (const float*)d_in[17];
    const float* outp_b    = (const float*)d_in[19];
    const float* norm1_g   = (const float*)d_in[20];
    const float* norm1_b   = (const float*)d_in[21];
    const float* ffn_b1    = (const float*)d_in[23];
    const float* ffn_b2    = (const float*)d_in[25];
    const float* norm3_g   = (const float*)d_in[26];
    const float* norm3_b   = (const float*)d_in[27];
    float* out = (float*)d_out;

    cudaFuncSetAttribute(tc_gemm_bf<false,false>, cudaFuncAttributeMaxDynamicSharedMemorySize, TCG_SMEM);
    cudaFuncSetAttribute(tc_gemm_bf<true,true>,   cudaFuncAttributeMaxDynamicSharedMemorySize, TCG_SMEM);

    void* p;
    #define SYMF(name) cudaGetSymbolAddress(&p, name); float* name##_p = (float*)p;
    #define SYMB(name) cudaGetSymbolAddress(&p, name); __nv_bfloat16* name##_p = (__nv_bfloat16*)p;
    SYMF(g_qkc) SYMF(g_v) SYMF(g_proj) SYMF(g_tgt2) SYMF(g_tgt3)
    SYMF(g_offaw) SYMF(g_value) SYMF(g_cbias)
    SYMB(g_qk_h) SYMB(g_qk_l) SYMB(g_tgt_h) SYMB(g_tgt_l)
    SYMB(g_att_h) SYMB(g_att_l) SYMB(g_query_h) SYMB(g_query_l)
    SYMB(g_tgt3_h) SYMB(g_tgt3_l) SYMB(g_ca_h) SYMB(g_ca_l)
    SYMB(g_ffn_h) SYMB(g_ffn_l) SYMB(g_src_h) SYMB(g_src_l)
    SYMB(g_wh) SYMB(g_wl)
    #undef SYMF
    #undef SYMB

    // 0) weight + input splits
    split_weights<<<(WTOT + 255)/256, 256>>>(
        (const float*)d_in[6], (const float*)d_in[8], (const float*)d_in[12],
        (const float*)d_in[14], (const float*)d_in[16], (const float*)d_in[18],
        (const float*)d_in[22], (const float*)d_in[24],
        off_b, aw_b, g_wh_p, g_wl_p, g_cbias_p);
    const int n4 = NQ * DM / 4;
    add_split_kernel<<<(n4 + 255)/256, 256>>>(tgt, query_pos, g_qk_h_p, g_qk_l_p,
                                              g_tgt_h_p, g_tgt_l_p, n4);
    const int ns4 = (int)((size_t)NSRC * DM / 4);
    split_kernel<<<(ns4 + 255)/256, 256>>>(src, g_src_h_p, g_src_l_p, ns4);

    // 1) self-attn: q|k merged (N=512), v
    gemm_bf(g_qk_h_p, g_qk_l_p, g_wh_p + OFF_SAIN, g_wl_p + OFF_SAIN, sa_in_b,
            g_qkc_p, 0, 0, NQ, 512, DM, false);
    gemm_bf(g_tgt_h_p, g_tgt_l_p, g_wh_p + OFF_SAIN + 131072, g_wl_p + OFF_SAIN + 131072,
            sa_in_b + 2*DM, g_v_p, 0, 0, NQ, DM, DM, false);
    attn_kernel<<<dim3((LQ + 127)/128, NB * NH), 128>>>(g_qkc_p, g_v_p, g_att_h_p, g_att_l_p);
    gemm_bf(g_att_h_p, g_att_l_p, g_wh_p + OFF_SAOUT, g_wl_p + OFF_SAOUT, sa_out_b,
            g_proj_p, 0, 0, NQ, DM, DM, false);
    ln_kernel<<<NQ, DM>>>(tgt, g_proj_p, norm2_g, norm2_b, g_tgt2_p, query_pos,
                          g_query_h_p, g_query_l_p);

    // 2) cross-attn: value, merged off|aw (N=384)
    gemm_bf(g_src_h_p, g_src_l_p, g_wh_p + OFF_VALW, g_wl_p + OFF_VALW, val_b,
            g_value_p, 0, 0, NSRC, DM, DM, false);
    gemm_bf(g_query_h_p, g_query_l_p, g_wh_p + OFF_OFFW, g_wl_p + OFF_OFFW, g_cbias_p,
            g_offaw_p, 0, 0, NQ, 384, DM, false);
    awsm_kernel<<<(NQ * NH + 255)/256, 256>>>(g_offaw_p);
    deform_kernel<<<NQ, dim3(32, 8)>>>(g_value_p, g_offaw_p, refpts, g_ca_h_p, g_ca_l_p);
    gemm_bf(g_ca_h_p, g_ca_l_p, g_wh_p + OFF_OUTPW, g_wl_p + OFF_OUTPW, outp_b,
            g_proj_p, 0, 0, NQ, DM, DM, false);
    ln_kernel<<<NQ, DM>>>(g_tgt2_p, g_proj_p, norm1_g, norm1_b, g_tgt3_p, nullptr,
                          g_tgt3_h_p, g_tgt3_l_p);

    // 3) FFN
    gemm_bf(g_tgt3_h_p, g_tgt3_l_p, g_wh_p + OFF_FFN1, g_wl_p + OFF_FFN1, ffn_b1,
            0, g_ffn_h_p, g_ffn_l_p, NQ, DFFN, DM, true);
    gemm_bf(g_ffn_h_p, g_ffn_l_p, g_wh_p + OFF_FFN2, g_wl_p + OFF_FFN2, ffn_b2,
            g_proj_p, 0, 0, NQ, DM, DFFN, false);
    ln_kernel<<<NQ, DM>>>(g_tgt3_p, g_proj_p, norm3_g, norm3_b, out, nullptr, nullptr, nullptr);
}

// round 7
// speedup vs baseline: 1.6767x; 1.6767x over previous
#include <cuda_runtime.h>
#include <cuda_bf16.h>
#include <math.h>
#include <stdint.h>

#define NB    8
#define LQ    1000
#define DM    256
#define NH    8
#define DH    32
#define NLV   4
#define NPT   4
#define LEN_IN 21760
#define DFFN  1024
#define NQ    (NB*LQ)    /* 8000 */
#define NSRC  (NB*LEN_IN) /* 174080 */

// ---------------- fp32 scratch ---------------------------------------------
__device__ float g_proj[NQ*DM];
__device__ float g_tgt2[NQ*DM];
__device__ float g_tgt3[NQ*DM];
__device__ float g_offaw[NQ*384];        // merged offsets|aw
__device__ float g_value[(size_t)NSRC*DM];
__device__ float g_cbias[384];

// ---------------- bf16 hi/lo split scratch ---------------------------------
__device__ __nv_bfloat16 g_qk_h[NQ*DM],   g_qk_l[NQ*DM];    // tgt+pos
__device__ __nv_bfloat16 g_tgt_h[NQ*DM],  g_tgt_l[NQ*DM];
__device__ __nv_bfloat16 g_qk2_h[NQ*512], g_qk2_l[NQ*512];  // q|k proj
__device__ __nv_bfloat16 g_v2_h[NQ*DM],   g_v2_l[NQ*DM];    // v proj
__device__ __nv_bfloat16 g_att_h[NQ*DM],  g_att_l[NQ*DM];
__device__ __nv_bfloat16 g_query_h[NQ*DM],g_query_l[NQ*DM];
__device__ __nv_bfloat16 g_tgt3_h[NQ*DM], g_tgt3_l[NQ*DM];
__device__ __nv_bfloat16 g_ca_h[NQ*DM],   g_ca_l[NQ*DM];
__device__ __nv_bfloat16 g_ffn_h[NQ*DFFN],g_ffn_l[NQ*DFFN];
__device__ __nv_bfloat16 g_src_h[(size_t)NSRC*DM], g_src_l[(size_t)NSRC*DM];

#define WTOT 1015808
#define OFF_SAIN  0
#define OFF_SAOUT 196608
#define OFF_OFFW  262144   /* off weights then aw weights: contiguous N=384 */
#define OFF_VALW  360448
#define OFF_OUTPW 425984
#define OFF_FFN1  491520
#define OFF_FFN2  753664
__device__ __nv_bfloat16 g_wh[WTOT], g_wl[WTOT];

// =================== helpers ===============================================
__device__ __forceinline__ uint32_t smem_u32(const void* p) {
    uint32_t a;
    asm("{ .reg .u64 t; cvta.to.shared.u64 t, %1; cvt.u32.u64 %0, t; }" : "=r"(a) : "l"(p));
    return a;
}
__device__ __forceinline__ void ldmx4(uint32_t addr, uint32_t* r) {
    asm volatile("ldmatrix.sync.aligned.m8n8.x4.shared.b16 {%0,%1,%2,%3}, [%4];"
                 : "=r"(r[0]), "=r"(r[1]), "=r"(r[2]), "=r"(r[3]) : "r"(addr));
}
__device__ __forceinline__ void ldmx4t(uint32_t addr, uint32_t* r) {
    asm volatile("ldmatrix.sync.aligned.m8n8.x4.trans.shared.b16 {%0,%1,%2,%3}, [%4];"
                 : "=r"(r[0]), "=r"(r[1]), "=r"(r[2]), "=r"(r[3]) : "r"(addr));
}
__device__ __forceinline__ void mma16816(float* d, const uint32_t* a, uint32_t b0, uint32_t b1) {
    asm volatile("mma.sync.aligned.m16n8k16.row.col.f32.bf16.bf16.f32 "
                 "{%0,%1,%2,%3}, {%4,%5,%6,%7}, {%8,%9}, {%0,%1,%2,%3};"
                 : "+f"(d[0]), "+f"(d[1]), "+f"(d[2]), "+f"(d[3])
                 : "r"(a[0]), "r"(a[1]), "r"(a[2]), "r"(a[3]), "r"(b0), "r"(b1));
}
__device__ __forceinline__ void cp16z(uint32_t dst, const void* src, bool v) {
    asm volatile("cp.async.cg.shared.global [%0], [%1], 16, %2;"
                 :: "r"(dst), "l"(src), "r"(v ? 16 : 0));
}
__device__ __forceinline__ void split2(float v, __nv_bfloat16& h, __nv_bfloat16& l) {
    h = __float2bfloat16(v);
    l = __float2bfloat16(v - __bfloat162float(h));
}
__device__ __forceinline__ float ex2f(float x) {
    float r; asm("ex2.approx.ftz.f32 %0, %1;" : "=f"(r) : "f"(x)); return r;
}
__device__ __forceinline__ uint32_t packbf(float a, float b) {
    __nv_bfloat162 p(__float2bfloat16(a), __float2bfloat16(b));
    return *(uint32_t*)&p;
}

// =================== bf16-split tensor GEMM (R4 config) ====================
// 128x128 tile, BK=32, 256 threads (8 warps, 32x64 warp tile), 2-stage ring.
#define TCSTR 40
#define TILE_AH 0
#define TILE_AL 10240
#define TILE_BH 20480
#define TILE_BL 30720
#define STAGE_TOTAL 40960
#define TCG_SMEM (2*STAGE_TOTAL)

__device__ __forceinline__ void stage_load(
    uint32_t sb, const __nv_bfloat16* Ah, const __nv_bfloat16* Al,
    const __nv_bfloat16* Bh, const __nv_bfloat16* Bl,
    int M, int N, int K, int rowBase, int colBase, int k0, int ldR, int ldC) {
    int gr = rowBase + ldR; bool av = gr < M; if (!av) gr = 0;
    const char* pa  = (const char*)(Ah + (size_t)gr * K + k0) + ldC;
    const char* pal = (const char*)(Al + (size_t)gr * K + k0) + ldC;
    uint32_t da  = sb + TILE_AH + ldR * 80 + ldC;
    uint32_t dal = sb + TILE_AL + ldR * 80 + ldC;
    cp16z(da, pa, av);        cp16z(da + 16, pa + 16, av);
    cp16z(dal, pal, av);      cp16z(dal + 16, pal + 16, av);
    int gc = colBase + ldR; bool bv = gc < N; if (!bv) gc = 0;
    const char* pb  = (const char*)(Bh + (size_t)gc * K + k0) + ldC;
    const char* pbl = (const char*)(Bl + (size_t)gc * K + k0) + ldC;
    uint32_t db  = sb + TILE_BH + ldR * 80 + ldC;
    uint32_t dbl = sb + TILE_BL + ldR * 80 + ldC;
    cp16z(db, pb, bv);        cp16z(db + 16, pb + 16, bv);
    cp16z(dbl, pbl, bv);      cp16z(dbl + 16, pbl + 16, bv);
    asm volatile("cp.async.commit_group;" ::: "memory");
}

template<bool RELU, bool SPLITOUT>
__global__ __launch_bounds__(256)
void tc_gemm_bf(const __nv_bfloat16* __restrict__ Ah, const __nv_bfloat16* __restrict__ Al,
                const __nv_bfloat16* __restrict__ Bh, const __nv_bfloat16* __restrict__ Bl,
                const float* __restrict__ bias, float* __restrict__ Cf,
                __nv_bfloat16* __restrict__ Chi, __nv_bfloat16* __restrict__ Clo,
                int M, int N, int K) {
    extern __shared__ char smem[];
    const uint32_t sbase = smem_u32(smem);
    const int tid  = threadIdx.x;
    const int lane = tid & 31;
    const int wid  = tid >> 5;
    const int warpM = wid & 3;
    const int warpN = wid >> 2;
    const int rowBase = blockIdx.y * 128;
    const int colBase = blockIdx.x * 128;
    const int ldR = tid >> 1;
    const int ldC = (tid & 1) * 32;

    const int aRow = (lane & 15);
    const int aColOff = (lane >> 4) * 8;
    const int bRow = (lane & 7) + ((lane >> 4) & 1) * 8;
    const int bColOff = ((lane >> 3) & 1) * 8;

    float acc[2][8][4];
    #pragma unroll
    for (int mt = 0; mt < 2; mt++)
        #pragma unroll
        for (int nt = 0; nt < 8; nt++)
            #pragma unroll
            for (int i = 0; i < 4; i++) acc[mt][nt][i] = 0.f;

    const int KC = K >> 5;
    stage_load(sbase, Ah, Al, Bh, Bl, M, N, K, rowBase, colBase, 0, ldR, ldC);

    for (int c = 0; c < KC; c++) {
        asm volatile("cp.async.wait_group 0;" ::: "memory");
        __syncthreads();
        if (c + 1 < KC)
            stage_load(sbase + ((c + 1) & 1) * STAGE_TOTAL, Ah, Al, Bh, Bl,
                       M, N, K, rowBase, colBase, (c + 1) << 5, ldR, ldC);

        const uint32_t sb = sbase + (c & 1) * STAGE_TOTAL;
        #pragma unroll
        for (int ks = 0; ks < 32; ks += 16) {
            uint32_t ah[2][4], al[2][4];
            #pragma unroll
            for (int mt = 0; mt < 2; mt++) {
                const int r0 = warpM * 32 + mt * 16;
                uint32_t off = (uint32_t)((r0 + aRow) * TCSTR + ks + aColOff) * 2;
                ldmx4(sb + TILE_AH + off, ah[mt]);
                ldmx4(sb + TILE_AL + off, al[mt]);
            }
            uint32_t bh[4][4], bl[4][4];
            #pragma unroll
            for (int nb = 0; nb < 4; nb++) {
                const int n0 = warpN * 64 + nb * 16;
                uint32_t off = (uint32_t)((n0 + bRow) * TCSTR + ks + bColOff) * 2;
                ldmx4(sb + TILE_BH + off, bh[nb]);
                ldmx4(sb + TILE_BL + off, bl[nb]);
            }
            #pragma unroll
            for (int mt = 0; mt < 2; mt++) {
                #pragma unroll
                for (int nt = 0; nt < 8; nt++) {
                    const int nb = nt >> 1, hi = (nt & 1) * 2;
                    mma16816(acc[mt][nt], ah[mt], bh[nb][hi], bh[nb][hi+1]);
                    mma16816(acc[mt][nt], ah[mt], bl[nb][hi], bl[nb][hi+1]);
                    mma16816(acc[mt][nt], al[mt], bh[nb][hi], bh[nb][hi+1]);
                }
            }
        }
    }

    #pragma unroll
    for (int mt = 0; mt < 2; mt++) {
        #pragma unroll
        for (int half = 0; half < 2; half++) {
            const int row = rowBase + warpM * 32 + mt * 16 + (lane >> 2) + half * 8;
            if (row < M) {
                #pragma unroll
                for (int nt = 0; nt < 8; nt++) {
                    const int col = colBase + warpN * 64 + nt * 8 + (lane & 3) * 2;
                    float ox = acc[mt][nt][half*2+0] + bias[col];
                    float oy = acc[mt][nt][half*2+1] + bias[col+1];
                    if (RELU) { ox = fmaxf(ox, 0.f); oy = fmaxf(oy, 0.f); }
                    if (SPLITOUT) {
                        __nv_bfloat16 hx, lx, hy, ly;
                        split2(ox, hx, lx); split2(oy, hy, ly);
                        *(__nv_bfloat162*)(Chi + (size_t)row * N + col) = __nv_bfloat162(hx, hy);
                        *(__nv_bfloat162*)(Clo + (size_t)row * N + col) = __nv_bfloat162(lx, ly);
                    } else {
                        *(float2*)(Cf + (size_t)row * N + col) = make_float2(ox, oy);
                    }
                }
            }
        }
    }
}

// =================== tensor-core flash self-attention ======================
// Block: 128 queries x one (b,h); 256 threads, warp w owns rows w*16..+15.
// S = Q@K^T (3-term split), online softmax in C-frags, P@V (3-term split).
#define ATT_QH 0
#define ATT_QL 10240
#define ATT_KV(st) (20480 + (st)*20480)
#define ATT_KH_O 0
#define ATT_KL_O 5120
#define ATT_VH_O 10240
#define ATT_VL_O 15360
#define ATT_SMEM (20480 + 2*20480)
#define KSCALE 0.25503486f   /* log2(e)/sqrt(32) */

__global__ __launch_bounds__(256)
void attn_mma(const __nv_bfloat16* __restrict__ qkh, const __nv_bfloat16* __restrict__ qkl,
              const __nv_bfloat16* __restrict__ vph, const __nv_bfloat16* __restrict__ vpl,
              __nv_bfloat16* __restrict__ oh, __nv_bfloat16* __restrict__ ol) {
    extern __shared__ char smem[];
    const uint32_t sb = smem_u32(smem);
    const int tid = threadIdx.x;
    const int lane = tid & 31;
    const int w = tid >> 5;
    const int g = lane >> 2, t4 = lane & 3;
    const int qbase = blockIdx.x * 128;
    const int b = blockIdx.y >> 3, h = blockIdx.y & 7;

    // ---- load Q (128 rows x 32 dims, h/l) ---------------------------------
    {
        const int r = tid >> 1, cb = (tid & 1) * 32;
        const int gr = qbase + r;
        const bool v = gr < LQ;
        const size_t rowo = ((size_t)(b * LQ + (v ? gr : 0)) * 512 + h * 32) * 2;
        cp16z(sb + ATT_QH + r * 80 + cb,      (const char*)qkh + rowo + cb, v);
        cp16z(sb + ATT_QH + r * 80 + cb + 16, (const char*)qkh + rowo + cb + 16, v);
        cp16z(sb + ATT_QL + r * 80 + cb,      (const char*)qkl + rowo + cb, v);
        cp16z(sb + ATT_QL + r * 80 + cb + 16, (const char*)qkl + rowo + cb + 16, v);
    }
    // ---- first K/V tile ----
    {
        const int r = tid >> 2, j = tid & 3;
        const bool v = r < LQ;
        const size_t ko = ((size_t)(b * LQ + (v ? r : 0)) * 512 + 256 + h * 32) * 2 + j * 16;
        const size_t vo = ((size_t)(b * LQ + (v ? r : 0)) * 256 + h * 32) * 2 + j * 16;
        cp16z(sb + ATT_KV(0) + ATT_KH_O + r * 80 + j * 16, (const char*)qkh + ko, v);
        cp16z(sb + ATT_KV(0) + ATT_KL_O + r * 80 + j * 16, (const char*)qkl + ko, v);
        cp16z(sb + ATT_KV(0) + ATT_VH_O + r * 80 + j * 16, (const char*)vph + vo, v);
        cp16z(sb + ATT_KV(0) + ATT_VL_O + r * 80 + j * 16, (const char*)vpl + vo, v);
    }
    asm volatile("cp.async.commit_group;" ::: "memory");

    float m0 = -1e30f, m1 = -1e30f, l0 = 0.f, l1 = 0.f;
    float o[4][4];
    #pragma unroll
    for (int vt = 0; vt < 4; vt++)
        #pragma unroll
        for (int i = 0; i < 4; i++) o[vt][i] = 0.f;

    uint32_t qh[2][4], ql[2][4];
    const int bRow = (lane & 7) + ((lane >> 4) & 1) * 8;
    const int bColOff = ((lane >> 3) & 1) * 8;
    const int NT = (LQ + 63) / 64;   // 16

    for (int ti = 0; ti < NT; ti++) {
        asm volatile("cp.async.wait_group 0;" ::: "memory");
        __syncthreads();
        if (ti == 0) {
            #pragma unroll
            for (int kf = 0; kf < 2; kf++) {
                uint32_t off = (uint32_t)((w * 16 + (lane & 15)) * TCSTR + kf * 16 + (lane >> 4) * 8) * 2;
                ldmx4(sb + ATT_QH + off, qh[kf]);
                ldmx4(sb + ATT_QL + off, ql[kf]);
            }
        }
        if (ti + 1 < NT) {
            const int kt = (ti + 1) * 64;
            const int r = tid >> 2, j = tid & 3;
            const int kr = kt + r;
            const bool v = kr < LQ;
            const size_t ko = ((size_t)(b * LQ + (v ? kr : 0)) * 512 + 256 + h * 32) * 2 + j * 16;
            const size_t vo = ((size_t)(b * LQ + (v ? kr : 0)) * 256 + h * 32) * 2 + j * 16;
            const uint32_t st = sb + ATT_KV((ti + 1) & 1);
            cp16z(st + ATT_KH_O + r * 80 + j * 16, (const char*)qkh + ko, v);
            cp16z(st + ATT_KL_O + r * 80 + j * 16, (const char*)qkl + ko, v);
            cp16z(st + ATT_VH_O + r * 80 + j * 16, (const char*)vph + vo, v);
            cp16z(st + ATT_VL_O + r * 80 + j * 16, (const char*)vpl + vo, v);
            asm volatile("cp.async.commit_group;" ::: "memory");
        }

        const uint32_t stg = sb + ATT_KV(ti & 1);
        const int kt = ti * 64;

        // ---- S = Q@K^T ----
        float s[8][4];
        #pragma unroll
        for (int nt = 0; nt < 8; nt++)
            #pragma unroll
            for (int i = 0; i < 4; i++) s[nt][i] = 0.f;
        #pragma unroll
        for (int kf = 0; kf < 2; kf++) {
            #pragma unroll
            for (int nb = 0; nb < 4; nb++) {
                uint32_t off = (uint32_t)((nb * 16 + bRow) * TCSTR + kf * 16 + bColOff) * 2;
                uint32_t kh[4], kl[4];
                ldmx4(stg + ATT_KH_O + off, kh);
                ldmx4(stg + ATT_KL_O + off, kl);
                #pragma unroll
                for (int hf = 0; hf < 2; hf++) {
                    const int nt = nb * 2 + hf;
                    mma16816(s[nt], qh[kf], kh[hf*2], kh[hf*2+1]);
                    mma16816(s[nt], qh[kf], kl[hf*2], kl[hf*2+1]);
                    mma16816(s[nt], ql[kf], kh[hf*2], kh[hf*2+1]);
                }
            }
        }

        // ---- scale + mask + online softmax ----
        const int validTiles = min(8, (LQ - kt) >> 3);
        float tmax0 = -1e30f, tmax1 = -1e30f;
        #pragma unroll
        for (int nt = 0; nt < 8; nt++) {
            if (nt < validTiles) {
                s[nt][0] *= KSCALE; s[nt][1] *= KSCALE;
                s[nt][2] *= KSCALE; s[nt][3] *= KSCALE;
            } else {
                s[nt][0] = s[nt][1] = s[nt][2] = s[nt][3] = -1e30f;
            }
            tmax0 = fmaxf(tmax0, fmaxf(s[nt][0], s[nt][1]));
            tmax1 = fmaxf(tmax1, fmaxf(s[nt][2], s[nt][3]));
        }
        tmax0 = fmaxf(tmax0, __shfl_xor_sync(0xffffffffu, tmax0, 1));
        tmax0 = fmaxf(tmax0, __shfl_xor_sync(0xffffffffu, tmax0, 2));
        tmax1 = fmaxf(tmax1, __shfl_xor_sync(0xffffffffu, tmax1, 1));
        tmax1 = fmaxf(tmax1, __shfl_xor_sync(0xffffffffu, tmax1, 2));
        const float mn0 = fmaxf(m0, tmax0), mn1 = fmaxf(m1, tmax1);
        const float c0 = ex2f(m0 - mn0), c1 = ex2f(m1 - mn1);
        m0 = mn0; m1 = mn1;
        l0 *= c0; l1 *= c1;
        #pragma unroll
        for (int vt = 0; vt < 4; vt++) {
            o[vt][0] *= c0; o[vt][1] *= c0; o[vt][2] *= c1; o[vt][3] *= c1;
        }

        // ---- P = exp2(S - m), pack to A-frags (hi/lo) ----
        uint32_t ph[4][4], pl[4][4];
        #pragma unroll
        for (int nt = 0; nt < 8; nt++) {
            float p0 = ex2f(s[nt][0] - mn0), p1 = ex2f(s[nt][1] - mn0);
            float p2 = ex2f(s[nt][2] - mn1), p3 = ex2f(s[nt][3] - mn1);
            l0 += p0 + p1; l1 += p2 + p3;
            __nv_bfloat16 h0,lo0,h1,lo1,h2,lo2,h3,lo3;
            split2(p0,h0,lo0); split2(p1,h1,lo1); split2(p2,h2,lo2); split2(p3,h3,lo3);
            const int ks = nt >> 1, base = (nt & 1) * 2;
            __nv_bfloat162 ph01(h0,h1), ph23(h2,h3), pl01(lo0,lo1), pl23(lo2,lo3);
            ph[ks][base+0] = *(uint32_t*)&ph01;
            ph[ks][base+1] = *(uint32_t*)&ph23;
            pl[ks][base+0] = *(uint32_t*)&pl01;
            pl[ks][base+1] = *(uint32_t*)&pl23;
        }

        // ---- O += P@V ----
        #pragma unroll
        for (int ks = 0; ks < 4; ks++) {
            const int krow = ks * 16 + (lane & 7) + ((lane >> 3) & 1) * 8;
            #pragma unroll
            for (int nh = 0; nh < 2; nh++) {
                uint32_t off = (uint32_t)(krow * TCSTR + nh * 16 + (lane >> 4) * 8) * 2;
                uint32_t vh[4], vl[4];
                ldmx4t(stg + ATT_VH_O + off, vh);
                ldmx4t(stg + ATT_VL_O + off, vl);
                #pragma unroll
                for (int sub = 0; sub < 2; sub++) {
                    const int vt = nh * 2 + sub;
                    mma16816(o[vt], ph[ks], vh[sub*2], vh[sub*2+1]);
                    mma16816(o[vt], ph[ks], vl[sub*2], vl[sub*2+1]);
                    mma16816(o[vt], pl[ks], vh[sub*2], vh[sub*2+1]);
                }
            }
        }
    }

    // ---- epilogue ----------------------------------------------------------
    l0 += __shfl_xor_sync(0xffffffffu, l0, 1);
    l0 += __shfl_xor_sync(0xffffffffu, l0, 2);
    l1 += __shfl_xor_sync(0xffffffffu, l1, 1);
    l1 += __shfl_xor_sync(0xffffffffu, l1, 2);
    const float inv0 = 1.f / l0, inv1 = 1.f / l1;
    const int r0 = qbase + w * 16 + g;
    const int r1 = r0 + 8;
    #pragma unroll
    for (int half = 0; half < 2; half++) {
        const int row = half ? r1 : r0;
        const float inv = half ? inv1 : inv0;
        if (row < LQ) {
            const size_t base = ((size_t)(b * LQ + row)) * DM + h * DH;
            #pragma unroll
            for (int vt = 0; vt < 4; vt++) {
                float vx = o[vt][half*2+0] * inv;
                float vy = o[vt][half*2+1] * inv;
                __nv_bfloat16 hx,lx,hy,ly;
                split2(vx,hx,lx); split2(vy,hy,ly);
                const size_t idx = base + vt * 8 + t4 * 2;
                *(__nv_bfloat162*)(oh + idx) = __nv_bfloat162(hx,hy);
                *(__nv_bfloat162*)(ol + idx) = __nv_bfloat162(lx,ly);
            }
        }
    }
}

// ---------------- weight splitter + combined bias --------------------------
__global__ void split_weights(const float* __restrict__ w0, const float* __restrict__ w1,
                              const float* __restrict__ w2, const float* __restrict__ w3,
                              const float* __restrict__ w4, const float* __restrict__ w5,
                              const float* __restrict__ w6, const float* __restrict__ w7,
                              const float* __restrict__ off_b, const float* __restrict__ aw_b,
                              __nv_bfloat16* __restrict__ hi, __nv_bfloat16* __restrict__ lo,
                              float* __restrict__ cbias) {
    int i = blockIdx.x * blockDim.x + threadIdx.x;
    if (i < 384) cbias[i] = (i < 256) ? off_b[i] : aw_b[i - 256];
    if (i >= WTOT) return;
    const float* src; int local;
    if      (i < OFF_SAOUT) { src = w0; local = i; }
    else if (i < OFF_OFFW)  { src = w1; local = i - OFF_SAOUT; }
    else if (i < OFF_VALW)  { src = (i < 327680) ? w2 : w3; local = (i < 327680) ? i - OFF_OFFW : i - 327680; }
    else if (i < OFF_OUTPW) { src = w4; local = i - OFF_VALW; }
    else if (i < OFF_FFN1)  { src = w5; local = i - OFF_OUTPW; }
    else if (i < OFF_FFN2)  { src = w6; local = i - OFF_FFN1; }
    else                    { src = w7; local = i - OFF_FFN2; }
    __nv_bfloat16 h, l;
    split2(src[local], h, l);
    hi[i] = h; lo[i] = l;
}

// ---------------- add + split: qk = tgt+pos; also split tgt ----------------
__global__ void add_split_kernel(const float* __restrict__ a, const float* __restrict__ b,
                                 __nv_bfloat16* __restrict__ qh, __nv_bfloat16* __restrict__ ql,
                                 __nv_bfloat16* __restrict__ th, __nv_bfloat16* __restrict__ tl,
                                 int n4) {
    int i = blockIdx.x * blockDim.x + threadIdx.x;
    if (i >= n4) return;
    float4 x = ((const float4*)a)[i];
    float4 y = ((const float4*)b)[i];
    float q0 = x.x + y.x, q1 = x.y + y.y, q2 = x.z + y.z, q3 = x.w + y.w;
    __nv_bfloat16 h0,l0,h1,l1,h2,l2,h3,l3;
    split2(q0,h0,l0); split2(q1,h1,l1); split2(q2,h2,l2); split2(q3,h3,l3);
    *(__nv_bfloat162*)(qh + i*4)     = __nv_bfloat162(h0,h1);
    *(__nv_bfloat162*)(qh + i*4 + 2) = __nv_bfloat162(h2,h3);
    *(__nv_bfloat162*)(ql + i*4)     = __nv_bfloat162(l0,l1);
    *(__nv_bfloat162*)(ql + i*4 + 2) = __nv_bfloat162(l2,l3);
    split2(x.x,h0,l0); split2(x.y,h1,l1); split2(x.z,h2,l2); split2(x.w,h3,l3);
    *(__nv_bfloat162*)(th + i*4)     = __nv_bfloat162(h0,h1);
    *(__nv_bfloat162*)(th + i*4 + 2) = __nv_bfloat162(h2,h3);
    *(__nv_bfloat162*)(tl + i*4)     = __nv_bfloat162(l0,l1);
    *(__nv_bfloat162*)(tl + i*4 + 2) = __nv_bfloat162(l2,l3);
}

// ---------------- generic fp32 -> hi/lo splitter (for src) -----------------
__global__ void split_kernel(const float* __restrict__ a,
                             __nv_bfloat16* __restrict__ hi, __nv_bfloat16* __restrict__ lo,
                             int n4) {
    int i = blockIdx.x * blockDim.x + threadIdx.x;
    if (i >= n4) return;
    float4 x = ((const float4*)a)[i];
    __nv_bfloat16 h0,l0,h1,l1,h2,l2,h3,l3;
    split2(x.x,h0,l0); split2(x.y,h1,l1); split2(x.z,h2,l2); split2(x.w,h3,l3);
    *(__nv_bfloat162*)(hi + i*4)     = __nv_bfloat162(h0,h1);
    *(__nv_bfloat162*)(hi + i*4 + 2) = __nv_bfloat162(h2,h3);
    *(__nv_bfloat162*)(lo + i*4)     = __nv_bfloat162(l0,l1);
    *(__nv_bfloat162*)(lo + i*4 + 2) = __nv_bfloat162(l2,l3);
}

// ---------------- LayerNorm(x+res) -> fp32 out (+ optional split of out+pos)
__global__ __launch_bounds__(256)
void ln_kernel(const float* __restrict__ x, const float* __restrict__ res,
               const float* __restrict__ g, const float* __restrict__ bta,
               float* __restrict__ out,
               const float* __restrict__ pos,
               __nv_bfloat16* __restrict__ hi, __nv_bfloat16* __restrict__ lo) {
    __shared__ float red[8];
    const int row = blockIdx.x, t = threadIdx.x;
    const size_t idx = (size_t)row * DM + t;
    float v = x[idx] + res[idx];

    float s = v;
    #pragma unroll
    for (int o = 16; o; o >>= 1) s += __shfl_xor_sync(0xffffffffu, s, o);
    if ((t & 31) == 0) red[t >> 5] = s;
    __syncthreads();
    float mean = 0.f;
    #pragma unroll
    for (int i = 0; i < 8; i++) mean += red[i];
    mean *= (1.f / DM);
    __syncthreads();

    float d = v - mean;
    float s2 = d * d;
    #pragma unroll
    for (int o = 16; o; o >>= 1) s2 += __shfl_xor_sync(0xffffffffu, s2, o);
    if ((t & 31) == 0) red[t >> 5] = s2;
    __syncthreads();
    float var = 0.f;
    #pragma unroll
    for (int i = 0; i < 8; i++) var += red[i];
    var *= (1.f / DM);

    float o = d * rsqrtf(var + 1e-5f) * g[t] + bta[t];
    out[idx] = o;
    if (hi) {
        float tq = pos ? o + pos[idx] : o;
        __nv_bfloat16 hh, ll;
        split2(tq, hh, ll);
        hi[idx] = hh; lo[idx] = ll;
    }
}

// ---------------- attention-weight softmax (aw at offset 256 of g_offaw) ---
__global__ void awsm_kernel(float* __restrict__ offaw) {
    int i = blockIdx.x * blockDim.x + threadIdx.x;
    if (i >= NQ * NH) return;
    float* p = offaw + (size_t)(i / NH) * 384 + 256 + (i % NH) * 16;
    float mx = -1e30f;
    #pragma unroll
    for (int j = 0; j < 16; j++) mx = fmaxf(mx, p[j]);
    float sm = 0.f, e[16];
    #pragma unroll
    for (int j = 0; j < 16; j++) { e[j] = __expf(p[j] - mx); sm += e[j]; }
    float inv = 1.f / sm;
    #pragma unroll
    for (int j = 0; j < 16; j++) p[j] = e[j] * inv;
}

// ---------------- MS-deformable sampling -----------------------------------
__global__ __launch_bounds__(256)
void deform_kernel(const float* __restrict__ value, const float* __restrict__ offaw,
                   const float* __restrict__ ref,
                   __nv_bfloat16* __restrict__ oh, __nv_bfloat16* __restrict__ ol) {
    const int qidx = blockIdx.x;
    const int b = qidx / LQ;
    const int h = threadIdx.y, d = threadIdx.x;

    const int starts[4] = {0, 16384, 20480, 21504};
    const int Wi[4]     = {128, 64, 32, 16};

    const float* vb = value + (size_t)b * LEN_IN * DM + h * DH + d;
    const size_t oq = (size_t)qidx;
    const float* offp = offaw + oq * 384;
    float acc = 0.f;

    #pragma unroll
    for (int lvl = 0; lvl < NLV; lvl++) {
        const float W = (float)Wi[lvl];
        const int   Wl = Wi[lvl];
        const int   st = starts[lvl];
        const float rx = ref[(oq * NLV + lvl) * 2 + 0];
        const float ry = ref[(oq * NLV + lvl) * 2 + 1];
        #pragma unroll
        for (int p = 0; p < NPT; p++) {
            const int oidx = ((h * NLV + lvl) * NPT + p) * 2;
            const float ox = offp[oidx + 0];
            const float oy = offp[oidx + 1];
            const float a  = offp[256 + h * 16 + lvl * 4 + p];
            const float x = (rx + ox / W) * W - 0.5f;
            const float y = (ry + oy / W) * W - 0.5f;
            const float x0f = floorf(x), y0f = floorf(y);
            const float lx = x - x0f, ly = y - y0f;
            const int x0 = (int)x0f, y0 = (int)y0f;

            const float w00 = (1.f - ly) * (1.f - lx);
            const float w01 = (1.f - ly) * lx;
            const float w10 = ly * (1.f - lx);
            const float w11 = ly * lx;

            const bool xv0 = (x0 >= 0) & (x0 < Wl);
            const bool xv1 = (x0 + 1 >= 0) & (x0 + 1 < Wl);
            const bool yv0 = (y0 >= 0) & (y0 < Wl);
            const bool yv1 = (y0 + 1 >= 0) & (y0 + 1 < Wl);

            if (yv0 & xv0) acc = fmaf(a * w00, vb[(size_t)(st + y0 * Wl + x0) * DM], acc);
            if (yv0 & xv1) acc = fmaf(a * w01, vb[(size_t)(st + y0 * Wl + x0 + 1) * DM], acc);
            if (yv1 & xv0) acc = fmaf(a * w10, vb[(size_t)(st + (y0 + 1) * Wl + x0) * DM], acc);
            if (yv1 & xv1) acc = fmaf(a * w11, vb[(size_t)(st + (y0 + 1) * Wl + x0 + 1) * DM], acc);
        }
    }
    __nv_bfloat16 hh, ll;
    split2(acc, hh, ll);
    oh[oq * DM + h * DH + d] = hh;
    ol[oq * DM + h * DH + d] = ll;
}

// ---------------- host-side orchestration ----------------------------------
enum GMode { GM_F32, GM_SPLIT, GM_RELU_SPLIT };
static inline void gemm_bf(const __nv_bfloat16* Ah, const __nv_bfloat16* Al,
                           const __nv_bfloat16* Bh, const __nv_bfloat16* Bl,
                           const float* bias, float* Cf,
                           __nv_bfloat16* Chi, __nv_bfloat16* Clo,
                           int M, int N, int K, GMode mode) {
    dim3 grid(N / 128, (M + 127) / 128);
    if (mode == GM_RELU_SPLIT)
        tc_gemm_bf<true, true><<<grid, 256, TCG_SMEM>>>(Ah, Al, Bh, Bl, bias, Cf, Chi, Clo, M, N, K);
    else if (mode == GM_SPLIT)
        tc_gemm_bf<false, true><<<grid, 256, TCG_SMEM>>>(Ah, Al, Bh, Bl, bias, Cf, Chi, Clo, M, N, K);
    else
        tc_gemm_bf<false, false><<<grid, 256, TCG_SMEM>>>(Ah, Al, Bh, Bl, bias, Cf, Chi, Clo, M, N, K);
}

extern "C" void kernel_launch(void* const* d_in, const int* in_sizes, int n_in,
                              void* d_out, int out_size) {
    (void)in_sizes; (void)n_in; (void)out_size;
    const float* tgt       = (const float*)d_in[0];
    const float* query_pos = (const float*)d_in[1];
    const float* refpts    = (const float*)d_in[2];
    const float* src       = (const float*)d_in[3];
    const float* sa_in_b   = (const float*)d_in[7];
    const float* sa_out_b  = (const float*)d_in[9];
    const float* norm2_g   = (const float*)d_in[10];
    const float* norm2_b   = (const float*)d_in[11];
    const float* off_b     = (const float*)d_in[13];
    const float* aw_b      = (const float*)d_in[15];
    const float* val_b     = (const float*)d_in[17];
    const float* outp_b    = (const float*)d_in[19];
    const float* norm1_g   = (const float*)d_in[20];
    const float* norm1_b   = (const float*)d_in[21];
    const float* ffn_b1    = (const float*)d_in[23];
    const float* ffn_b2    = (const float*)d_in[25];
    const float* norm3_g   = (const float*)d_in[26];
    const float* norm3_b   = (const float*)d_in[27];
    float* out = (float*)d_out;

    cudaFuncSetAttribute(tc_gemm_bf<false,false>, cudaFuncAttributeMaxDynamicSharedMemorySize, TCG_SMEM);
    cudaFuncSetAttribute(tc_gemm_bf<false,true>,  cudaFuncAttributeMaxDynamicSharedMemorySize, TCG_SMEM);
    cudaFuncSetAttribute(tc_gemm_bf<true,true>,   cudaFuncAttributeMaxDynamicSharedMemorySize, TCG_SMEM);
    cudaFuncSetAttribute(attn_mma, cudaFuncAttributeMaxDynamicSharedMemorySize, ATT_SMEM);

    void* p;
    #define SYMF(name) cudaGetSymbolAddress(&p, name); float* name##_p = (float*)p;
    #define SYMB(name) cudaGetSymbolAddress(&p, name); __nv_bfloat16* name##_p = (__nv_bfloat16*)p;
    SYMF(g_proj) SYMF(g_tgt2) SYMF(g_tgt3)
    SYMF(g_offaw) SYMF(g_value) SYMF(g_cbias)
    SYMB(g_qk_h) SYMB(g_qk_l) SYMB(g_tgt_h) SYMB(g_tgt_l)
    SYMB(g_qk2_h) SYMB(g_qk2_l) SYMB(g_v2_h) SYMB(g_v2_l)
    SYMB(g_att_h) SYMB(g_att_l) SYMB(g_query_h) SYMB(g_query_l)
    SYMB(g_tgt3_h) SYMB(g_tgt3_l) SYMB(g_ca_h) SYMB(g_ca_l)
    SYMB(g_ffn_h) SYMB(g_ffn_l) SYMB(g_src_h) SYMB(g_src_l)
    SYMB(g_wh) SYMB(g_wl)
    #undef SYMF
    #undef SYMB

    // 0) weight + input splits
    split_weights<<<(WTOT + 255)/256, 256>>>(
        (const float*)d_in[6], (const float*)d_in[8], (const float*)d_in[12],
        (const float*)d_in[14], (const float*)d_in[16], (const float*)d_in[18],
        (const float*)d_in[22], (const float*)d_in[24],
        off_b, aw_b, g_wh_p, g_wl_p, g_cbias_p);
    const int n4 = NQ * DM / 4;
    add_split_kernel<<<(n4 + 255)/256, 256>>>(tgt, query_pos, g_qk_h_p, g_qk_l_p,
                                              g_tgt_h_p, g_tgt_l_p, n4);
    const int ns4 = (int)((size_t)NSRC * DM / 4);
    split_kernel<<<(ns4 + 255)/256, 256>>>(src, g_src_h_p, g_src_l_p, ns4);

    // 1) self-attn: merged q|k proj (split out), v proj (split out)
    gemm_bf(g_qk_h_p, g_qk_l_p, g_wh_p + OFF_SAIN, g_wl_p + OFF_SAIN, sa_in_b,
            0, g_qk2_h_p, g_qk2_l_p, NQ, 512, DM, GM_SPLIT);
    gemm_bf(g_tgt_h_p, g_tgt_l_p, g_wh_p + OFF_SAIN + 131072, g_wl_p + OFF_SAIN + 131072,
            sa_in_b + 2*DM, 0, g_v2_h_p, g_v2_l_p, NQ, DM, DM, GM_SPLIT);
    attn_mma<<<dim3(8, NB * NH), 256, ATT_SMEM>>>(g_qk2_h_p, g_qk2_l_p, g_v2_h_p, g_v2_l_p,
                                                  g_att_h_p, g_att_l_p);
    gemm_bf(g_att_h_p, g_att_l_p, g_wh_p + OFF_SAOUT, g_wl_p + OFF_SAOUT, sa_out_b,
            g_proj_p, 0, 0, NQ, DM, DM, GM_F32);
    ln_kernel<<<NQ, DM>>>(tgt, g_proj_p, norm2_g, norm2_b, g_tgt2_p, query_pos,
                          g_query_h_p, g_query_l_p);

    // 2) cross-attn
    gemm_bf(g_src_h_p, g_src_l_p, g_wh_p + OFF_VALW, g_wl_p + OFF_VALW, val_b,
            g_value_p, 0, 0, NSRC, DM, DM, GM_F32);
    gemm_bf(g_query_h_p, g_query_l_p, g_wh_p + OFF_OFFW, g_wl_p + OFF_OFFW, g_cbias_p,
            g_offaw_p, 0, 0, NQ, 384, DM, GM_F32);
    awsm_kernel<<<(NQ * NH + 255)/256, 256>>>(g_offaw_p);
    deform_kernel<<<NQ, dim3(32, 8)>>>(g_value_p, g_offaw_p, refpts, g_ca_h_p, g_ca_l_p);
    gemm_bf(g_ca_h_p, g_ca_l_p, g_wh_p + OFF_OUTPW, g_wl_p + OFF_OUTPW, outp_b,
            g_proj_p, 0, 0, NQ, DM, DM, GM_F32);
    ln_kernel<<<NQ, DM>>>(g_tgt2_p, g_proj_p, norm1_g, norm1_b, g_tgt3_p, nullptr,
                          g_tgt3_h_p, g_tgt3_l_p);

    // 3) FFN
    gemm_bf(g_tgt3_h_p, g_tgt3_l_p, g_wh_p + OFF_FFN1, g_wl_p + OFF_FFN1, ffn_b1,
            0, g_ffn_h_p, g_ffn_l_p, NQ, DFFN, DM, GM_RELU_SPLIT);
    gemm_bf(g_ffn_h_p, g_ffn_l_p, g_wh_p + OFF_FFN2, g_wl_p + OFF_FFN2, ffn_b2,
            g_proj_p, 0, 0, NQ, DM, DFFN, GM_F32);
    ln_kernel<<<NQ, DM>>>(g_tgt3_p, g_proj_p, norm3_g, norm3_b, out, nullptr, nullptr, nullptr);
}